// round 6
// baseline (speedup 1.0000x reference)
#include <cuda_runtime.h>
#include <cuda_pipeline.h>
#include <mma.h>

using namespace nvcuda;

#define NN     50000
#define F0     128
#define HC     256
#define NHEADS 4
#define CH     64
#define EMAX   900000
#define SLOPE  0.2f

// ---------------- scratch (static device globals; no allocs allowed) -------
__device__ float g_h[(long long)NN * HC];   // post-GEMM features, current layer
__device__ float g_x[(long long)NN * HC];   // layer output / next layer input
__device__ float g_as[NN * NHEADS];         // a_src per node/head
__device__ float g_ad[NN * NHEADS];         // a_dst per node/head
__device__ int   g_rowptr[NN + 1];          // CSR by destination
__device__ int   g_off[NN];                 // counts / running offsets
__device__ int   g_col[EMAX];               // src node per CSR slot

// ---------------- CSR build ------------------------------------------------
__global__ void zero_off_kernel() {
    int i = blockIdx.x * blockDim.x + threadIdx.x;
    if (i < NN) g_off[i] = 0;
}

__global__ void count_kernel(const int* __restrict__ dst, int E) {
    int e = blockIdx.x * blockDim.x + threadIdx.x;
    if (e < E) atomicAdd(&g_off[dst[e]], 1);
}

__global__ void scan_kernel() {
    __shared__ int part[1024];
    int t = threadIdx.x;
    const int CHK = (NN + 1023) / 1024;
    int lo = t * CHK;
    int hi = lo + CHK; if (hi > NN) hi = NN;
    if (lo > NN) lo = NN;
    int s = 0;
    for (int i = lo; i < hi; i++) s += g_off[i];
    part[t] = s;
    __syncthreads();
    for (int d = 1; d < 1024; d <<= 1) {
        int v = (t >= d) ? part[t - d] : 0;
        __syncthreads();
        part[t] += v;
        __syncthreads();
    }
    int pre = (t == 0) ? 0 : part[t - 1];
    for (int i = lo; i < hi; i++) {
        int c = g_off[i];
        g_rowptr[i] = pre;
        g_off[i]    = pre;
        pre += c;
    }
    if (t == 1023) g_rowptr[NN] = part[1023];
}

__global__ void scatter_kernel(const int* __restrict__ src,
                               const int* __restrict__ dst, int E) {
    int e = blockIdx.x * blockDim.x + threadIdx.x;
    if (e < E) {
        int p = atomicAdd(&g_off[dst[e]], 1);
        g_col[p] = src[e];
    }
}

// ---------------- TF32 tensor-core GEMM, cp.async double-buffered ----------
// BM=128, BN=64, BK=32. 256 threads = 8 warps (4m x 2n), warp tile 32x32 =
// 2x2 wmma m16n16k8 tf32 fragments. Raw fp32 tiles staged via cp.async;
// tf32 rounding applied in-fragment. OOB rows are clamped (outputs guarded).

#define BM 128
#define BN 64
#define BK 32
#define APAD 4
#define BPAD 4
#define A_LD (BK + APAD)     // 36
#define B_LD (BN + BPAD)     // 68
#define A_TILE (BM * A_LD)   // floats per A buffer
#define B_TILE (BK * B_LD)   // floats per B buffer
#define GEMM_SMEM_BYTES ((2 * A_TILE + 2 * B_TILE) * 4)

__global__ __launch_bounds__(256)
void gemm_tf32_kernel(const float* __restrict__ A,
                      const float* __restrict__ B,
                      float* __restrict__ Cmat, int M, int K) {
    extern __shared__ float smem[];
    float* Asm = smem;                 // [2][BM][A_LD]
    float* Bsm = smem + 2 * A_TILE;    // [2][BK][B_LD]

    int tid  = threadIdx.x;
    int warp = tid >> 5;
    int wm   = warp >> 1;        // 0..3 -> m offset wm*32
    int wn   = warp & 1;         // 0..1 -> n offset wn*32

    int m0 = blockIdx.y * BM;
    int n0 = blockIdx.x * BN;

    // A load mapping: row = tid>>1 (0..127), kbase = (tid&1)*16 (4 x 16B)
    int ar = tid >> 1;
    int ak = (tid & 1) * 16;
    int arow = m0 + ar; if (arow >= M) arow = M - 1;   // clamp; output guarded
    // B load mapping: row = tid>>3 (0..31), cbase = (tid&7)*8 (2 x 16B)
    int br = tid >> 3;
    int bc = (tid & 7) * 8;

    wmma::fragment<wmma::accumulator, 16, 16, 8, float> c[2][2];
#pragma unroll
    for (int i = 0; i < 2; i++)
#pragma unroll
        for (int j = 0; j < 2; j++)
            wmma::fill_fragment(c[i][j], 0.0f);

    const int nk = K / BK;

    // prefetch tile 0 into buffer 0
    {
        const float* ap = A + (long long)arow * K + ak;
        float* ad = Asm + ar * A_LD + ak;
#pragma unroll
        for (int i = 0; i < 4; i++)
            __pipeline_memcpy_async(ad + i * 4, ap + i * 4, 16);
        const float* bp = B + (long long)br * HC + n0 + bc;
        float* bd = Bsm + br * B_LD + bc;
#pragma unroll
        for (int i = 0; i < 2; i++)
            __pipeline_memcpy_async(bd + i * 4, bp + i * 4, 16);
        __pipeline_commit();
    }

    int buf = 0;
    for (int it = 0; it < nk; it++) {
        __pipeline_wait_prior(0);
        __syncthreads();

        if (it + 1 < nk) {
            int k1 = (it + 1) * BK;
            const float* ap = A + (long long)arow * K + k1 + ak;
            float* ad = Asm + (buf ^ 1) * A_TILE + ar * A_LD + ak;
#pragma unroll
            for (int i = 0; i < 4; i++)
                __pipeline_memcpy_async(ad + i * 4, ap + i * 4, 16);
            const float* bp = B + (long long)(k1 + br) * HC + n0 + bc;
            float* bd = Bsm + (buf ^ 1) * B_TILE + br * B_LD + bc;
#pragma unroll
            for (int i = 0; i < 2; i++)
                __pipeline_memcpy_async(bd + i * 4, bp + i * 4, 16);
            __pipeline_commit();
        }

        const float* Ab = Asm + buf * A_TILE;
        const float* Bb = Bsm + buf * B_TILE;
#pragma unroll
        for (int kk = 0; kk < BK; kk += 8) {
            wmma::fragment<wmma::matrix_a, 16, 16, 8,
                           wmma::precision::tf32, wmma::row_major> a[2];
            wmma::fragment<wmma::matrix_b, 16, 16, 8,
                           wmma::precision::tf32, wmma::row_major> b[2];
#pragma unroll
            for (int i = 0; i < 2; i++) {
                wmma::load_matrix_sync(a[i], Ab + (wm * 32 + i * 16) * A_LD + kk, A_LD);
#pragma unroll
                for (int t = 0; t < a[i].num_elements; t++)
                    a[i].x[t] = wmma::__float_to_tf32(a[i].x[t]);
            }
#pragma unroll
            for (int j = 0; j < 2; j++) {
                wmma::load_matrix_sync(b[j], Bb + kk * B_LD + wn * 32 + j * 16, B_LD);
#pragma unroll
                for (int t = 0; t < b[j].num_elements; t++)
                    b[j].x[t] = wmma::__float_to_tf32(b[j].x[t]);
            }
#pragma unroll
            for (int i = 0; i < 2; i++)
#pragma unroll
                for (int j = 0; j < 2; j++)
                    wmma::mma_sync(c[i][j], a[i], b[j], c[i][j]);
        }
        buf ^= 1;
    }

    // epilogue: per-fragment row guard (M % 16 == 0 makes this exact)
#pragma unroll
    for (int i = 0; i < 2; i++) {
        int row0 = m0 + wm * 32 + i * 16;
        if (row0 >= M) continue;
#pragma unroll
        for (int j = 0; j < 2; j++) {
            int col0 = n0 + wn * 32 + j * 16;
            wmma::store_matrix_sync(&Cmat[(long long)row0 * HC + col0],
                                    c[i][j], HC, wmma::mem_row_major);
        }
    }
}

// ---------------- attention logits: a_src/a_dst per (node, head) -----------
__global__ void attn_kernel(const float* __restrict__ att_src,
                            const float* __restrict__ att_dst) {
    int gw = (blockIdx.x * blockDim.x + threadIdx.x) >> 5;
    int lane = threadIdx.x & 31;
    if (gw >= NN * NHEADS) return;
    int n = gw >> 2, hd = gw & 3;
    const float* hp = &g_h[(long long)n * HC + hd * CH];
    float h0 = hp[lane], h1 = hp[lane + 32];
    float s1 = h0 * att_src[hd * CH + lane] + h1 * att_src[hd * CH + lane + 32];
    float s2 = h0 * att_dst[hd * CH + lane] + h1 * att_dst[hd * CH + lane + 32];
#pragma unroll
    for (int d = 16; d; d >>= 1) {
        s1 += __shfl_xor_sync(0xffffffffu, s1, d);
        s2 += __shfl_xor_sync(0xffffffffu, s2, d);
    }
    if (lane == 0) {
        g_as[n * NHEADS + hd] = s1;
        g_ad[n * NHEADS + hd] = s2;
    }
}

// ---------------- aggregation: warp per destination node -------------------
__global__ void agg_kernel(const float* __restrict__ bias, float* __restrict__ out) {
    int warp = (blockIdx.x * blockDim.x + threadIdx.x) >> 5;
    int lane = threadIdx.x & 31;
    if (warp >= NN) return;
    int n = warp;
    int beg = g_rowptr[n], end = g_rowptr[n + 1];
    float4 ad4 = *(const float4*)&g_ad[n * 4];

    float m0 = -1e30f, m1 = -1e30f, m2 = -1e30f, m3 = -1e30f;
    for (int e = beg + lane; e < end; e += 32) {
        int s = g_col[e];
        float4 a4 = *(const float4*)&g_as[s * 4];
        float v;
        v = a4.x + ad4.x; v = v > 0.f ? v : SLOPE * v; m0 = fmaxf(m0, v);
        v = a4.y + ad4.y; v = v > 0.f ? v : SLOPE * v; m1 = fmaxf(m1, v);
        v = a4.z + ad4.z; v = v > 0.f ? v : SLOPE * v; m2 = fmaxf(m2, v);
        v = a4.w + ad4.w; v = v > 0.f ? v : SLOPE * v; m3 = fmaxf(m3, v);
    }
#pragma unroll
    for (int d = 16; d; d >>= 1) {
        m0 = fmaxf(m0, __shfl_xor_sync(0xffffffffu, m0, d));
        m1 = fmaxf(m1, __shfl_xor_sync(0xffffffffu, m1, d));
        m2 = fmaxf(m2, __shfl_xor_sync(0xffffffffu, m2, d));
        m3 = fmaxf(m3, __shfl_xor_sync(0xffffffffu, m3, d));
    }
    int hd = lane >> 3;
    float mh  = (hd == 0) ? m0 : (hd == 1) ? m1 : (hd == 2) ? m2 : m3;
    float adh = (hd == 0) ? ad4.x : (hd == 1) ? ad4.y : (hd == 2) ? ad4.z : ad4.w;

    int cbase = lane * 8;
    float acc[8] = {0.f, 0.f, 0.f, 0.f, 0.f, 0.f, 0.f, 0.f};
    float den = 0.f;
    for (int e = beg; e < end; e++) {
        int s = g_col[e];
        float av = g_as[s * 4 + hd];
        float ee = av + adh;
        ee = ee > 0.f ? ee : SLOPE * ee;
        float ex = __expf(ee - mh);
        den += ex;
        const float4* hp = (const float4*)&g_h[(long long)s * HC + cbase];
        float4 h0 = hp[0], h1 = hp[1];
        acc[0] += ex * h0.x; acc[1] += ex * h0.y; acc[2] += ex * h0.z; acc[3] += ex * h0.w;
        acc[4] += ex * h1.x; acc[5] += ex * h1.y; acc[6] += ex * h1.z; acc[7] += ex * h1.w;
    }
    float inv = 1.f / (den + 1e-16f);
    float4 b0 = *(const float4*)&bias[cbase];
    float4 b1 = *(const float4*)&bias[cbase + 4];
    float4 o0, o1;
    o0.x = fmaxf(acc[0] * inv + b0.x, 0.f);
    o0.y = fmaxf(acc[1] * inv + b0.y, 0.f);
    o0.z = fmaxf(acc[2] * inv + b0.z, 0.f);
    o0.w = fmaxf(acc[3] * inv + b0.w, 0.f);
    o1.x = fmaxf(acc[4] * inv + b1.x, 0.f);
    o1.y = fmaxf(acc[5] * inv + b1.y, 0.f);
    o1.z = fmaxf(acc[6] * inv + b1.z, 0.f);
    o1.w = fmaxf(acc[7] * inv + b1.w, 0.f);
    *(float4*)&out[(long long)n * HC + cbase]     = o0;
    *(float4*)&out[(long long)n * HC + cbase + 4] = o1;
}

// ---------------- launcher -------------------------------------------------
extern "C" void kernel_launch(void* const* d_in, const int* in_sizes, int n_in,
                              void* d_out, int out_size) {
    const float* x  = (const float*)d_in[0];
    const int*   ei = (const int*)d_in[1];
    int E = in_sizes[1] / 2;
    const int* src = ei;
    const int* dst = ei + E;

    const float* W[3]  = {(const float*)d_in[2], (const float*)d_in[6],  (const float*)d_in[10]};
    const float* AS[3] = {(const float*)d_in[3], (const float*)d_in[7],  (const float*)d_in[11]};
    const float* AD[3] = {(const float*)d_in[4], (const float*)d_in[8],  (const float*)d_in[12]};
    const float* BI[3] = {(const float*)d_in[5], (const float*)d_in[9],  (const float*)d_in[13]};
    float* out = (float*)d_out;

    float* gx = nullptr;
    float* gh = nullptr;
    cudaGetSymbolAddress((void**)&gx, g_x);
    cudaGetSymbolAddress((void**)&gh, g_h);

    cudaFuncSetAttribute(gemm_tf32_kernel,
                         cudaFuncAttributeMaxDynamicSharedMemorySize,
                         GEMM_SMEM_BYTES);

    // CSR build (edge_index is identical for all layers)
    zero_off_kernel<<<(NN + 255) / 256, 256>>>();
    count_kernel<<<(E + 255) / 256, 256>>>(dst, E);
    scan_kernel<<<1, 1024>>>();
    scatter_kernel<<<(E + 255) / 256, 256>>>(src, dst, E);

    dim3 ggrid(HC / BN, (NN + BM - 1) / BM);
    int attn_blocks = (NN * NHEADS * 32 + 255) / 256;
    int agg_blocks  = (NN + 7) / 8;

    // layer 0 (K = 128)
    gemm_tf32_kernel<<<ggrid, 256, GEMM_SMEM_BYTES>>>(x, W[0], gh, NN, F0);
    attn_kernel<<<attn_blocks, 256>>>(AS[0], AD[0]);
    agg_kernel<<<agg_blocks, 256>>>(BI[0], gx);

    // layer 1 (K = 256)
    gemm_tf32_kernel<<<ggrid, 256, GEMM_SMEM_BYTES>>>(gx, W[1], gh, NN, HC);
    attn_kernel<<<attn_blocks, 256>>>(AS[1], AD[1]);
    agg_kernel<<<agg_blocks, 256>>>(BI[1], gx);

    // layer 2 (K = 256), write final output
    gemm_tf32_kernel<<<ggrid, 256, GEMM_SMEM_BYTES>>>(gx, W[2], gh, NN, HC);
    attn_kernel<<<attn_blocks, 256>>>(AS[2], AD[2]);
    agg_kernel<<<agg_blocks, 256>>>(BI[2], out);
}